// round 3
// baseline (speedup 1.0000x reference)
#include <cuda_runtime.h>
#include <math.h>

#define SEQ_LEN 16384
#define BATCH   32
#define DM      128
#define HN      256
#define THRESH  0.001f

#define RPB   128                 // rows per block
#define NBLK  (SEQ_LEN / RPB)     // 128 blocks
#define TPB   512                 // 16 warps, 8 rows per warp
#define NST   132                 // node smem row stride (floats; k*NST*4 % 16 == 0 for LDS.128)
#define HST   258                 // hyper smem row stride (floats; bank = (2k+lane)%32, conflict-free)

#define NODE_SH_F (DM * NST)      // 16896 floats
#define HYP_SH_F  (DM * HST)      // 33024 floats
#define SMEM_F    (NODE_SH_F + HYP_SH_F + RPB)
#define SMEM_B    (SMEM_F * 4)    // ~200.2 KB

__device__ __forceinline__ unsigned long long splat2(float x) {
    unsigned r = __float_as_uint(x);
    unsigned long long d;
    asm("mov.b64 %0, {%1, %2};" : "=l"(d) : "r"(r), "r"(r));
    return d;
}

__device__ __forceinline__ void fma2(unsigned long long& acc,
                                     unsigned long long a, unsigned long long b) {
    asm("fma.rn.f32x2 %0, %1, %2, %0;" : "+l"(acc) : "l"(a), "l"(b));
}

// One output row: relu*mask -> softmax -> exact top-8 (jax ties: lowest h wins)
// -> threshold. Warp-wide: lane holds h = lane + 32*j, j=0..7.
__device__ __forceinline__ void process_row(int row, const float* vin, float m,
                                            int lane, float* __restrict__ out)
{
    float v[8];
    unsigned ub[8];
#pragma unroll
    for (int j = 0; j < 8; ++j) {
        float x = fmaxf(vin[j], 0.0f) * m;
        v[j] = x;
        // non-negative floats: bit pattern is order-monotone; kill -0
        ub[j] = (x == 0.0f) ? 0u : __float_as_uint(x);
    }

    unsigned lmb = ub[0];
#pragma unroll
    for (int j = 1; j < 8; ++j) lmb = (ub[j] > lmb) ? ub[j] : lmb;
    unsigned gmb = __reduce_max_sync(0xffffffffu, lmb);
    float rowmax = __uint_as_float(gmb);

    float e[8];
    float ls = 0.0f;
#pragma unroll
    for (int j = 0; j < 8; ++j) { e[j] = expf(v[j] - rowmax); ls += e[j]; }
#pragma unroll
    for (int o = 16; o; o >>= 1) ls += __shfl_xor_sync(0xffffffffu, ls, o);

    // exact top-8: repeated warp argmax on (value desc, h asc)
    unsigned selmask = 0;
    int bj = 0; unsigned bv = ub[0];
#pragma unroll
    for (int j = 1; j < 8; ++j) if (ub[j] > bv) { bv = ub[j]; bj = j; }
#pragma unroll 1
    for (int it = 0; it < 8; ++it) {
        unsigned cand = (bj >= 0) ? bv : 0u;
        unsigned g  = __reduce_max_sync(0xffffffffu, cand);
        unsigned hc = (bj >= 0 && cand == g) ? (unsigned)(bj * 32 + lane) : 0xffffffffu;
        unsigned gh = __reduce_min_sync(0xffffffffu, hc);
        if (hc == gh) {
            selmask |= (1u << bj);
            bv = 0u; bj = -1;
#pragma unroll
            for (int j = 0; j < 8; ++j)
                if (!(selmask & (1u << j)) && (bj < 0 || ub[j] > bv)) { bv = ub[j]; bj = j; }
        }
    }

    float* op = out + (size_t)row * HN + lane;
#pragma unroll
    for (int j = 0; j < 8; ++j) {
        float soft = e[j] / ls;
        op[32 * j] = (((selmask >> j) & 1u) && (soft > THRESH)) ? 1.0f : 0.0f;
    }
}

__global__ __launch_bounds__(TPB, 1)
void hg_kernel(const float* __restrict__ mask, const float* __restrict__ node,
               const float* __restrict__ hyper, float* __restrict__ out)
{
    extern __shared__ float sm[];
    float* node_sh = sm;                          // [DM][NST], node_sh[d*NST + r]
    float* hyp_sh  = sm + NODE_SH_F;              // [DM][HST], hyp_sh[d*HST + h]
    float* mp_sh   = sm + NODE_SH_F + HYP_SH_F;   // [RPB]

    const int t  = threadIdx.x;
    const int n0 = blockIdx.x * RPB;

    // batch-mean mask penalty for this block's rows (sequential b order, as jax)
    if (t < RPB) {
        float s = 0.0f;
        const float* mc = mask + n0 + t;
#pragma unroll
        for (int b = 0; b < BATCH; ++b) s += mc[b * SEQ_LEN];
        mp_sh[t] = s / 32.0f;
    }
    // node tile, k-major (transposed): coalesced global reads
    for (int i = t; i < RPB * DM; i += TPB) {
        int r = i >> 7, d = i & (DM - 1);
        node_sh[d * NST + r] = node[(size_t)(n0 + r) * DM + d];
    }
    // full hyper matrix, k-major
    for (int i = t; i < HN * DM; i += TPB) {
        int h = i >> 7, d = i & (DM - 1);
        hyp_sh[d * HST + h] = hyper[i];
    }
    __syncthreads();

    const int lane = t & 31;
    const int w    = t >> 5;          // 0..15, warp owns rows [8w, 8w+8)

    // acc[j][i] = f32x2 { dot(row 8w+2i, h=lane+32j), dot(row 8w+2i+1, h) }
    // each half is a plain sequential fp32 sum over k (matches jax rounding).
    unsigned long long acc[8][4];
#pragma unroll
    for (int j = 0; j < 8; ++j)
#pragma unroll
        for (int i = 0; i < 4; ++i) acc[j][i] = 0ull;

    const float* np = node_sh + 8 * w;    // + k*NST : 8 contiguous rows (32B, 16B-aligned)
    const float* hp = hyp_sh + lane;      // + k*HST + 32j : conflict-free banks
#pragma unroll 2
    for (int k = 0; k < DM; ++k) {
        ulonglong2 a = *reinterpret_cast<const ulonglong2*>(np);       // rows 0-3
        ulonglong2 b = *reinterpret_cast<const ulonglong2*>(np + 4);   // rows 4-7
        unsigned long long nv[4] = { a.x, a.y, b.x, b.y };
        unsigned long long hs[8];
#pragma unroll
        for (int j = 0; j < 8; ++j) hs[j] = splat2(hp[32 * j]);
#pragma unroll
        for (int j = 0; j < 8; ++j)
#pragma unroll
            for (int i = 0; i < 4; ++i) fma2(acc[j][i], hs[j], nv[i]);
        np += NST;
        hp += HST;
    }

#pragma unroll
    for (int rp = 0; rp < 4; ++rp) {
        float vlo[8], vhi[8];
#pragma unroll
        for (int j = 0; j < 8; ++j) {
            vlo[j] = __uint_as_float((unsigned)(acc[j][rp] & 0xffffffffull));
            vhi[j] = __uint_as_float((unsigned)(acc[j][rp] >> 32));
        }
        int r0 = 8 * w + 2 * rp;
        process_row(n0 + r0,     vlo, mp_sh[r0],     lane, out);
        process_row(n0 + r0 + 1, vhi, mp_sh[r0 + 1], lane, out);
    }
}

extern "C" void kernel_launch(void* const* d_in, const int* in_sizes, int n_in,
                              void* d_out, int out_size)
{
    // metadata order: [0] features (unused), [1] mask, [2] node_embeds, [3] hyper_embeds
    const float* mask  = (const float*)d_in[1];
    const float* node  = (const float*)d_in[2];
    const float* hyper = (const float*)d_in[3];
    float* out = (float*)d_out;

    cudaFuncSetAttribute(hg_kernel, cudaFuncAttributeMaxDynamicSharedMemorySize, SMEM_B);
    hg_kernel<<<NBLK, TPB, SMEM_B>>>(mask, node, hyper, out);
}

// round 6
// speedup vs baseline: 1.4279x; 1.4279x over previous
#include <cuda_runtime.h>
#include <math.h>

#define SEQ_LEN 16384
#define BATCH   32
#define DM      128
#define HN      256
#define THRESH  0.001f

#define RPB     128                 // rows per block
#define NBLK    (SEQ_LEN / RPB)     // 128 blocks
#define TPB     512                 // 16 warps, 8 rows per warp
#define KCHUNK  64                  // hyper tile k-chunk

#define NDS     264                 // floats per k-row of DUPLICATED node (256 data + pad, 16B-aligned rows)
#define HST     258                 // floats per kk-row of hyper chunk
#define NODE_F  (DM * NDS)          // 33792 floats (135168 B) — all 128 k, rows duplicated
#define HYP_F   (KCHUNK * HST)      // 16512 floats (66048 B)  — one k-chunk
#define SMEM_F  (NODE_F + HYP_F + RPB)
#define SMEM_B  (SMEM_F * 4)        // 201728 B

typedef unsigned long long ull;

__device__ __forceinline__ void fma2(ull& acc, ull a, ull b) {
    asm("fma.rn.f32x2 %0, %1, %2, %0;" : "+l"(acc) : "l"(a), "l"(b));
}

// One output row. Lane owns h pairs: element e (0..7) -> h = 64*(e>>1) + 2*lane + (e&1).
// relu*maskmean -> softmax -> exact top-8 (jax ties: lowest h wins) -> threshold.
__device__ __forceinline__ void process_row(int row, const float* vin, float m,
                                            int lane, float* __restrict__ out)
{
    float v[8];
    unsigned ub[8];
#pragma unroll
    for (int e = 0; e < 8; ++e) {
        float x = fmaxf(vin[e], 0.0f) * m;
        v[e] = x;
        // non-negative floats: bits are order-monotone; kill -0
        ub[e] = (x == 0.0f) ? 0u : __float_as_uint(x);
    }

    unsigned lmb = ub[0];
#pragma unroll
    for (int e = 1; e < 8; ++e) lmb = (ub[e] > lmb) ? ub[e] : lmb;
    unsigned gmb = __reduce_max_sync(0xffffffffu, lmb);
    float rowmax = __uint_as_float(gmb);

    float ex[8];
    float ls = 0.0f;
#pragma unroll
    for (int e = 0; e < 8; ++e) { ex[e] = expf(v[e] - rowmax); ls += ex[e]; }
#pragma unroll
    for (int o = 16; o; o >>= 1) ls += __shfl_xor_sync(0xffffffffu, ls, o);

    // exact top-8: repeated warp argmax on (value desc, h asc)
    unsigned selmask = 0;
    int be = 0; unsigned bv = ub[0];
#pragma unroll
    for (int e = 1; e < 8; ++e) if (ub[e] > bv) { bv = ub[e]; be = e; }
#pragma unroll 1
    for (int it = 0; it < 8; ++it) {
        unsigned cand = (be >= 0) ? bv : 0u;
        unsigned g  = __reduce_max_sync(0xffffffffu, cand);
        unsigned hc = (be >= 0 && cand == g)
                      ? (unsigned)(64 * (be >> 1) + 2 * lane + (be & 1)) : 0xffffffffu;
        unsigned gh = __reduce_min_sync(0xffffffffu, hc);
        if (hc == gh) {
            selmask |= (1u << be);
            bv = 0u; be = -1;
#pragma unroll
            for (int e = 0; e < 8; ++e)
                if (!(selmask & (1u << e)) && (be < 0 || ub[e] > bv)) { bv = ub[e]; be = e; }
        }
    }

    float* op = out + (size_t)row * HN + 2 * lane;
#pragma unroll
    for (int j = 0; j < 4; ++j) {
        float2 r2;
        r2.x = (((selmask >> (2 * j)) & 1u)     && (ex[2 * j]     / ls > THRESH)) ? 1.0f : 0.0f;
        r2.y = (((selmask >> (2 * j + 1)) & 1u) && (ex[2 * j + 1] / ls > THRESH)) ? 1.0f : 0.0f;
        *reinterpret_cast<float2*>(op + 64 * j) = r2;
    }
}

__global__ __launch_bounds__(TPB, 1)
void hg_kernel(const float* __restrict__ mask, const float* __restrict__ node,
               const float* __restrict__ hyper, float* __restrict__ out)
{
    extern __shared__ float sm[];
    float* node_sh = sm;                    // [DM][NDS] : node_sh[k*NDS + 2r] = node_sh[.. + 2r+1] = node[r][k]
    float* hyp_sh  = sm + NODE_F;           // [KCHUNK][HST] : hyp_sh[kk*HST + h] = hyper[h][kbase+kk]
    float* mp_sh   = sm + NODE_F + HYP_F;   // [RPB]

    const int t  = threadIdx.x;
    const int n0 = blockIdx.x * RPB;

    // batch-mean mask penalty (sequential b order, matches jax)
    if (t < RPB) {
        float s = 0.0f;
        const float* mc = mask + n0 + t;
#pragma unroll
        for (int b = 0; b < BATCH; ++b) s += mc[b * SEQ_LEN];
        mp_sh[t] = s / 32.0f;
    }
    // node tile, k-major, DUPLICATED along rows (coalesced global reads)
    for (int i = t; i < RPB * DM; i += TPB) {
        int r = i >> 7, d = i & (DM - 1);
        float v = node[(size_t)(n0 + r) * DM + d];
        node_sh[d * NDS + 2 * r]     = v;
        node_sh[d * NDS + 2 * r + 1] = v;
    }

    const int lane = t & 31;
    const int w    = t >> 5;                 // 0..15, warp owns rows [8w, 8w+8)

    // acc[r][j]: f32x2 { sim(row 8w+r, h=64j+2lane), sim(row, h+1) }
    // each half is a plain sequential fp32 FMA chain over k.
    ull acc[8][4];
#pragma unroll
    for (int r = 0; r < 8; ++r)
#pragma unroll
        for (int j = 0; j < 4; ++j) acc[r][j] = 0ull;

#pragma unroll 1
    for (int c = 0; c < 2; ++c) {
        __syncthreads();   // c=0: nothing to protect in hyp region; c=1: all warps done reading chunk 0
        // hyper chunk c, k-major (coalesced: consecutive t -> consecutive kk)
        for (int i = t; i < HN * KCHUNK; i += TPB) {
            int h = i >> 6, kk = i & (KCHUNK - 1);
            hyp_sh[kk * HST + h] = hyper[(size_t)h * DM + c * KCHUNK + kk];
        }
        __syncthreads();   // chunk (and, at c=0, node/mp tiles) visible

        const float* nrow = node_sh + c * KCHUNK * NDS + 16 * w;
        const float* hrow = hyp_sh + 2 * lane;
#pragma unroll 4
        for (int kk = 0; kk < KCHUNK; ++kk) {
            // 8 dup-pairs for rows 8w..8w+7 : 4x LDS.128 (broadcast)
            ull nd[8];
#pragma unroll
            for (int p = 0; p < 4; ++p) {
                ulonglong2 q = *reinterpret_cast<const ulonglong2*>(nrow + 4 * p);
                nd[2 * p]     = q.x;
                nd[2 * p + 1] = q.y;
            }
            // 4 adjacent-h pairs : 4x LDS.64 (conflict-free)
            ull hs[4];
#pragma unroll
            for (int j = 0; j < 4; ++j)
                hs[j] = *reinterpret_cast<const ull*>(hrow + 64 * j);
#pragma unroll
            for (int r = 0; r < 8; ++r)
#pragma unroll
                for (int j = 0; j < 4; ++j) fma2(acc[r][j], nd[r], hs[j]);
            nrow += NDS;
            hrow += HST;
        }
    }

    // epilogue: fully static acc indexing
#pragma unroll
    for (int r = 0; r < 8; ++r) {
        float vin[8];
#pragma unroll
        for (int j = 0; j < 4; ++j) {
            vin[2 * j]     = __uint_as_float((unsigned)(acc[r][j] & 0xffffffffull));
            vin[2 * j + 1] = __uint_as_float((unsigned)(acc[r][j] >> 32));
        }
        int rr = 8 * w + r;
        process_row(n0 + rr, vin, mp_sh[rr], lane, out);
    }
}

extern "C" void kernel_launch(void* const* d_in, const int* in_sizes, int n_in,
                              void* d_out, int out_size)
{
    // metadata order: [0] features (unused), [1] mask, [2] node_embeds, [3] hyper_embeds
    const float* mask  = (const float*)d_in[1];
    const float* node  = (const float*)d_in[2];
    const float* hyper = (const float*)d_in[3];
    float* out = (float*)d_out;

    cudaFuncSetAttribute(hg_kernel, cudaFuncAttributeMaxDynamicSharedMemorySize, SMEM_B);
    hg_kernel<<<NBLK, TPB, SMEM_B>>>(mask, node, hyper, out);
}

// round 7
// speedup vs baseline: 1.4558x; 1.0196x over previous
#include <cuda_runtime.h>
#include <math.h>

#define SEQ_LEN 16384
#define BATCH   32
#define DM      128
#define HN      256
#define THRESH  0.001f

#define RPB     128                 // rows per block
#define NBLK    (SEQ_LEN / RPB)     // 128 blocks
#define TPB     512                 // 16 warps, 8 rows per warp
#define KCHUNK  64                  // hyper tile k-chunk

#define NDS     264                 // floats per k-row of duplicated node (1056 B, 16B-divisible)
#define HST     258                 // floats per kk-row of hyper chunk (1032 B, 8B-divisible)
#define NDS_B   (NDS * 4)           // 1056
#define HST_B   (HST * 4)           // 1032

#define NODE_F  ((DM + 1) * NDS)      // +1 pad row for one-ahead prefetch
#define HYP_F   ((KCHUNK + 1) * HST)  // +1 pad row for one-ahead prefetch
#define SMEM_F  (NODE_F + HYP_F + RPB)
#define SMEM_B  (SMEM_F * 4)          // 203816 B

typedef unsigned long long ull;

// ---- raw shared loads with immediate offsets (no address ALU, direct 64b pairs) ----
#define LDND1(d0, d1, off, IMM) \
    asm volatile("ld.shared.v2.u64 {%0,%1}, [%2+%3];" \
                 : "=l"(d0), "=l"(d1) : "r"(off), "n"(IMM))
#define LD_ND(nd, off, IMM) do { \
    LDND1(nd[0], nd[1], off, (IMM));      \
    LDND1(nd[2], nd[3], off, (IMM) + 16); \
    LDND1(nd[4], nd[5], off, (IMM) + 32); \
    LDND1(nd[6], nd[7], off, (IMM) + 48); } while (0)

#define LDHS1(d, off, IMM) \
    asm volatile("ld.shared.u64 %0, [%1+%2];" : "=l"(d) : "r"(off), "n"(IMM))
#define LD_HS(hs, off, IMM) do { \
    LDHS1(hs[0], off, (IMM));       LDHS1(hs[1], off, (IMM) + 256); \
    LDHS1(hs[2], off, (IMM) + 512); LDHS1(hs[3], off, (IMM) + 768); } while (0)

// 16 packed fp32x2 FMAs in one block: rows R0..R3 (dup pairs) x 4 h-pairs.
#define FMA16(A0, A1, A2, A3, N, NB, H) \
    asm("fma.rn.f32x2 %0, %16, %20, %0;\n\t"  \
        "fma.rn.f32x2 %1, %16, %21, %1;\n\t"  \
        "fma.rn.f32x2 %2, %16, %22, %2;\n\t"  \
        "fma.rn.f32x2 %3, %16, %23, %3;\n\t"  \
        "fma.rn.f32x2 %4, %17, %20, %4;\n\t"  \
        "fma.rn.f32x2 %5, %17, %21, %5;\n\t"  \
        "fma.rn.f32x2 %6, %17, %22, %6;\n\t"  \
        "fma.rn.f32x2 %7, %17, %23, %7;\n\t"  \
        "fma.rn.f32x2 %8, %18, %20, %8;\n\t"  \
        "fma.rn.f32x2 %9, %18, %21, %9;\n\t"  \
        "fma.rn.f32x2 %10, %18, %22, %10;\n\t" \
        "fma.rn.f32x2 %11, %18, %23, %11;\n\t" \
        "fma.rn.f32x2 %12, %19, %20, %12;\n\t" \
        "fma.rn.f32x2 %13, %19, %21, %13;\n\t" \
        "fma.rn.f32x2 %14, %19, %22, %14;\n\t" \
        "fma.rn.f32x2 %15, %19, %23, %15;"     \
        : "+l"(A0[0]), "+l"(A0[1]), "+l"(A0[2]), "+l"(A0[3]), \
          "+l"(A1[0]), "+l"(A1[1]), "+l"(A1[2]), "+l"(A1[3]), \
          "+l"(A2[0]), "+l"(A2[1]), "+l"(A2[2]), "+l"(A2[3]), \
          "+l"(A3[0]), "+l"(A3[1]), "+l"(A3[2]), "+l"(A3[3])  \
        : "l"(N[(NB) + 0]), "l"(N[(NB) + 1]), "l"(N[(NB) + 2]), "l"(N[(NB) + 3]), \
          "l"(H[0]), "l"(H[1]), "l"(H[2]), "l"(H[3]))

// One output row. Lane owns h: element e (0..7) -> h = 64*(e>>1) + 2*lane + (e&1).
// relu*maskmean -> softmax -> exact top-8 (jax ties: lowest h wins) -> threshold.
__device__ __forceinline__ void process_row(int row, const float* vin, float m,
                                            int lane, float* __restrict__ out)
{
    float v[8];
    unsigned ub[8];
#pragma unroll
    for (int e = 0; e < 8; ++e) {
        float x = fmaxf(vin[e], 0.0f) * m;
        v[e] = x;
        ub[e] = (x == 0.0f) ? 0u : __float_as_uint(x);   // nonneg: bits order-monotone
    }

    unsigned lmb = ub[0];
#pragma unroll
    for (int e = 1; e < 8; ++e) lmb = (ub[e] > lmb) ? ub[e] : lmb;
    unsigned gmb = __reduce_max_sync(0xffffffffu, lmb);
    float rowmax = __uint_as_float(gmb);

    float ex[8];
    float ls = 0.0f;
#pragma unroll
    for (int e = 0; e < 8; ++e) { ex[e] = expf(v[e] - rowmax); ls += ex[e]; }
#pragma unroll
    for (int o = 16; o; o >>= 1) ls += __shfl_xor_sync(0xffffffffu, ls, o);

    unsigned selmask = 0;
    int be = 0; unsigned bv = ub[0];
#pragma unroll
    for (int e = 1; e < 8; ++e) if (ub[e] > bv) { bv = ub[e]; be = e; }
#pragma unroll 1
    for (int it = 0; it < 8; ++it) {
        unsigned cand = (be >= 0) ? bv : 0u;
        unsigned g  = __reduce_max_sync(0xffffffffu, cand);
        unsigned hc = (be >= 0 && cand == g)
                      ? (unsigned)(64 * (be >> 1) + 2 * lane + (be & 1)) : 0xffffffffu;
        unsigned gh = __reduce_min_sync(0xffffffffu, hc);
        if (hc == gh) {
            selmask |= (1u << be);
            bv = 0u; be = -1;
#pragma unroll
            for (int e = 0; e < 8; ++e)
                if (!(selmask & (1u << e)) && (be < 0 || ub[e] > bv)) { bv = ub[e]; be = e; }
        }
    }

    float* op = out + (size_t)row * HN + 2 * lane;
#pragma unroll
    for (int j = 0; j < 4; ++j) {
        float2 r2;
        r2.x = (((selmask >> (2 * j)) & 1u)     && (ex[2 * j]     / ls > THRESH)) ? 1.0f : 0.0f;
        r2.y = (((selmask >> (2 * j + 1)) & 1u) && (ex[2 * j + 1] / ls > THRESH)) ? 1.0f : 0.0f;
        *reinterpret_cast<float2*>(op + 64 * j) = r2;
    }
}

__global__ __launch_bounds__(TPB, 1)
void hg_kernel(const float* __restrict__ mask, const float* __restrict__ node,
               const float* __restrict__ hyper, float* __restrict__ out)
{
    extern __shared__ float sm[];
    float* node_sh = sm;                    // [(DM+1)][NDS], node_sh[k*NDS + 2r] = node_sh[..+2r+1]
    float* hyp_sh  = sm + NODE_F;           // [(KCHUNK+1)][HST]
    float* mp_sh   = sm + NODE_F + HYP_F;   // [RPB]

    const int t  = threadIdx.x;
    const int n0 = blockIdx.x * RPB;

    // batch-mean mask penalty (sequential b order, matches jax)
    if (t < RPB) {
        float s = 0.0f;
        const float* mc = mask + n0 + t;
#pragma unroll
        for (int b = 0; b < BATCH; ++b) s += mc[b * SEQ_LEN];
        mp_sh[t] = s / 32.0f;
    }
    // node tile, k-major, duplicated along rows (coalesced global reads)
    for (int i = t; i < RPB * DM; i += TPB) {
        int r = i >> 7, d = i & (DM - 1);
        float v = node[(size_t)(n0 + r) * DM + d];
        node_sh[d * NDS + 2 * r]     = v;
        node_sh[d * NDS + 2 * r + 1] = v;
    }

    const int lane = t & 31;
    const int w    = t >> 5;                 // warp owns rows [8w, 8w+8)

    const unsigned sbase = (unsigned)__cvta_generic_to_shared(sm);
    const unsigned nbase = sbase + 64u * (unsigned)w;            // node_sh + 16w floats
    const unsigned hbase = sbase + (unsigned)(NODE_F * 4) + 8u * (unsigned)lane;

    // acc[r][j]: f32x2 { sim(row 8w+r, h=2lane+64j), sim(row, h+1) }
    // each half is one sequential fp32 FMA chain over k (matches the passing rounding).
    ull acc[8][4];
#pragma unroll
    for (int r = 0; r < 8; ++r)
#pragma unroll
        for (int j = 0; j < 4; ++j) acc[r][j] = 0ull;

#pragma unroll 1
    for (int c = 0; c < 2; ++c) {
        __syncthreads();   // c=1: all warps done reading chunk 0
        for (int i = t; i < HN * KCHUNK; i += TPB) {
            int h = i >> 6, kk = i & (KCHUNK - 1);
            hyp_sh[kk * HST + h] = hyper[(size_t)h * DM + c * KCHUNK + kk];
        }
        __syncthreads();   // chunk (and, at c=0, node/mp tiles) visible

        unsigned noff = nbase + (unsigned)(c * KCHUNK * NDS_B);
        unsigned hoff = hbase;

        ull nd0[8], nd1[8], hs0[4], hs1[4];
        LD_ND(nd0, noff, 0);
        LD_HS(hs0, hoff, 0);
#pragma unroll 1
        for (int kp = 0; kp < KCHUNK / 2; ++kp) {
            // prefetch kk+1 while consuming kk
            LD_ND(nd1, noff, NDS_B);
            LD_HS(hs1, hoff, HST_B);
            FMA16(acc[0], acc[1], acc[2], acc[3], nd0, 0, hs0);
            FMA16(acc[4], acc[5], acc[6], acc[7], nd0, 4, hs0);
            // prefetch kk+2 while consuming kk+1 (last iter reads pad rows; unused)
            LD_ND(nd0, noff, 2 * NDS_B);
            LD_HS(hs0, hoff, 2 * HST_B);
            FMA16(acc[0], acc[1], acc[2], acc[3], nd1, 0, hs1);
            FMA16(acc[4], acc[5], acc[6], acc[7], nd1, 4, hs1);
            noff += 2 * NDS_B;
            hoff += 2 * HST_B;
        }
    }

    // epilogue: fully static acc indexing
#pragma unroll
    for (int r = 0; r < 8; ++r) {
        float vin[8];
#pragma unroll
        for (int j = 0; j < 4; ++j) {
            vin[2 * j]     = __uint_as_float((unsigned)(acc[r][j] & 0xffffffffull));
            vin[2 * j + 1] = __uint_as_float((unsigned)(acc[r][j] >> 32));
        }
        int rr = 8 * w + r;
        process_row(n0 + rr, vin, mp_sh[rr], lane, out);
    }
}

extern "C" void kernel_launch(void* const* d_in, const int* in_sizes, int n_in,
                              void* d_out, int out_size)
{
    // metadata order: [0] features (unused), [1] mask, [2] node_embeds, [3] hyper_embeds
    const float* mask  = (const float*)d_in[1];
    const float* node  = (const float*)d_in[2];
    const float* hyper = (const float*)d_in[3];
    float* out = (float*)d_out;

    cudaFuncSetAttribute(hg_kernel, cudaFuncAttributeMaxDynamicSharedMemorySize, SMEM_B);
    hg_kernel<<<NBLK, TPB, SMEM_B>>>(mask, node, hyper, out);
}